// round 15
// baseline (speedup 1.0000x reference)
#include <cuda_runtime.h>
#include <cuda_bf16.h>
#include <cstdint>

#define BB    2
#define LQ    4096
#define CDIM  768
#define GH    64
#define GW    64
#define NHEAD 6
#define NPNT  4
#define HD    128
#define MROWS 8192      // B*Lq == B*H*W
#define NOA   72        // off(48) + attn(24) columns
#define NPAD  96        // padded N rows for small GEMM weights
#define KITERS 12       // 768 / 64
#define STAGES 3
#define A_SBYTES 16384      // 128 rows x 128B
#define B_SBYTES 8192       // 64 rows x 128B
#define STAGE_BYTES (A_SBYTES + B_SBYTES)   // 24576
#define SMEM_DYN (STAGES * STAGE_BYTES)     // 73728
#define LNROWS (2 * MROWS)
#define PREPBLKS (1153 + 288)

// ---------------- scratch (device globals; no allocation allowed) -------------
__device__ __align__(16) __nv_bfloat16 g_q[MROWS * CDIM];
__device__ __align__(16) __nv_bfloat16 g_f[MROWS * CDIM];
__device__ __align__(16) __nv_bfloat16 g_value[MROWS * CDIM];
__device__ __align__(16) __nv_bfloat16 g_sampled[MROWS * CDIM];
__device__ __align__(16) float         g_raw[MROWS * NOA];
__device__ __align__(16) __nv_bfloat16 g_wvT[CDIM * CDIM];   // [N][K]
__device__ __align__(16) __nv_bfloat16 g_woT[CDIM * CDIM];   // [N][K]
__device__ __align__(16) __nv_bfloat16 g_woaT[NPAD * CDIM];  // [N=96][K]
__device__ __align__(16) float         g_boa[NPAD];

// ---------------- PTX helpers -------------------------------------------------
__device__ __forceinline__ uint32_t smem_u32(const void* p) {
    uint32_t a;
    asm("{ .reg .u64 t; cvta.to.shared.u64 t, %1; cvt.u32.u64 %0, t; }" : "=r"(a) : "l"(p));
    return a;
}
__device__ __forceinline__ void cpasync16(uint32_t s, const void* g) {
    asm volatile("cp.async.cg.shared.global [%0], [%1], 16;" :: "r"(s), "l"(g));
}
__device__ __forceinline__ void cpasync16z(uint32_t s, const void* g, int srcsz) {
    asm volatile("cp.async.cg.shared.global [%0], [%1], 16, %2;" :: "r"(s), "l"(g), "r"(srcsz));
}
#define CP_COMMIT() asm volatile("cp.async.commit_group;" ::: "memory")
#define CP_WAIT(n)  asm volatile("cp.async.wait_group %0;" :: "n"(n) : "memory")

__device__ __forceinline__ void ldsm4(uint32_t r[4], uint32_t addr) {
    asm volatile("ldmatrix.sync.aligned.m8n8.x4.shared.b16 {%0,%1,%2,%3}, [%4];"
                 : "=r"(r[0]), "=r"(r[1]), "=r"(r[2]), "=r"(r[3]) : "r"(addr));
}
__device__ __forceinline__ void mma16816(float c[4], const uint32_t a[4], uint32_t b0, uint32_t b1) {
    asm volatile(
        "mma.sync.aligned.m16n8k16.row.col.f32.bf16.bf16.f32 "
        "{%0,%1,%2,%3},{%4,%5,%6,%7},{%8,%9},{%0,%1,%2,%3};\n"
        : "+f"(c[0]), "+f"(c[1]), "+f"(c[2]), "+f"(c[3])
        : "r"(a[0]), "r"(a[1]), "r"(a[2]), "r"(a[3]), "r"(b0), "r"(b1));
}

// ---------------- fused LN + weight prep (single launch) ----------------------
__global__ __launch_bounds__(256) void ln_prep_kernel(
    const float* __restrict__ x, const float* __restrict__ feat,
    const float* __restrict__ qw, const float* __restrict__ qb,
    const float* __restrict__ fw, const float* __restrict__ fb,
    const float* __restrict__ wv, const float* __restrict__ wo,
    const float* __restrict__ woff, const float* __restrict__ watt,
    const float* __restrict__ boff, const float* __restrict__ batt) {
    int blkid = blockIdx.x;
    int tid = threadIdx.x;
    if (blkid < LNROWS) {
        if (tid >= 192) return;
        int row = blkid;
        int t = tid;
        const float *src, *w, *bb;
        __nv_bfloat16* dst;
        if (row < MROWS) {
            src = x + (long)row * CDIM; w = qw; bb = qb; dst = g_q + (long)row * CDIM;
        } else {
            int r = row - MROWS;
            src = feat + (long)r * CDIM; w = fw; bb = fb; dst = g_f + (long)r * CDIM;
        }
        float4 v = *(const float4*)(src + t * 4);
        float s  = v.x + v.y + v.z + v.w;
        float ss = v.x * v.x + v.y * v.y + v.z * v.z + v.w * v.w;
        #pragma unroll
        for (int o = 16; o > 0; o >>= 1) {
            s  += __shfl_xor_sync(0xffffffffu, s,  o);
            ss += __shfl_xor_sync(0xffffffffu, ss, o);
        }
        __shared__ float sm[12];
        if ((t & 31) == 0) { sm[t >> 5] = s; sm[(t >> 5) + 6] = ss; }
        __syncthreads();
        float S = 0.f, SS = 0.f;
        #pragma unroll
        for (int i = 0; i < 6; i++) { S += sm[i]; SS += sm[i + 6]; }
        float mean = S * (1.f / 768.f);
        float var  = SS * (1.f / 768.f) - mean * mean;
        float inv  = rsqrtf(var + 1e-6f);
        float4 wv4 = *(const float4*)(w + t * 4);
        float4 bv4 = *(const float4*)(bb + t * 4);
        __nv_bfloat162 p0 = __floats2bfloat162_rn((v.x - mean) * inv * wv4.x + bv4.x,
                                                  (v.y - mean) * inv * wv4.y + bv4.y);
        __nv_bfloat162 p1 = __floats2bfloat162_rn((v.z - mean) * inv * wv4.z + bv4.z,
                                                  (v.w - mean) * inv * wv4.w + bv4.w);
        uint2 pk = make_uint2(*(uint32_t*)&p0, *(uint32_t*)&p1);
        *(uint2*)(dst + t * 4) = pk;
        return;
    }
    int blk = blkid - LNROWS;
    if (blk < 1152) {
        __shared__ float t[32][33];
        int z = blk / 576, rem = blk % 576;
        const float* src = z ? wo : wv;
        __nv_bfloat16* dst = z ? g_woT : g_wvT;
        int bx = (rem % 24) * 32, by = (rem / 24) * 32;
        int tx = tid & 31, ty = tid >> 5;          // 32 x 8
        #pragma unroll
        for (int i = 0; i < 32; i += 8)
            t[ty + i][tx] = src[(long)(by + ty + i) * CDIM + bx + tx];
        __syncthreads();
        #pragma unroll
        for (int i = 0; i < 32; i += 8)
            dst[(long)(bx + ty + i) * CDIM + by + tx] = __float2bfloat16(t[tx][ty + i]);
    } else if (blk == 1152) {
        if (tid < NPAD)
            g_boa[tid] = (tid < 48) ? boff[tid] : (tid < NOA) ? batt[tid - 48] : 0.f;
    } else {
        int i = (blk - 1153) * 256 + tid;
        if (i < NPAD * CDIM) {
            int n = i / CDIM, k = i % CDIM;
            float v = (n < 48) ? woff[k * 48 + n] : (n < NOA) ? watt[k * 24 + (n - 48)] : 0.f;
            g_woaT[i] = __float2bfloat16(v);
        }
    }
}

// ---------------- mma.sync GEMM: CTA 128x64, 8 warps 32x32, 3 CTA/SM ----------
// 3-stage cp.async, k-chunk 64, swizzled 128B rows. Balanced LDS/tensor pipes.
// sel 0: y<12: g_f @ wvT -> g_value (bf16,+bias); y>=12: g_q @ woaT -> g_raw
// sel 2: g_sampled @ woT, out = x + gamma*(acc+bias)
__global__ __launch_bounds__(256, 3) void gemm_tc(
    int sel,
    const float* __restrict__ bias_in,
    const float* __restrict__ xres, const float* __restrict__ gamma,
    float* __restrict__ outF)
{
    extern __shared__ __align__(16) char smem[];
    const uint32_t sa = smem_u32(smem);

    const int tid = threadIdx.x;
    const int warp = tid >> 5, lane = tid & 31;
    const int wm = warp >> 1, wn = warp & 1;       // 4 x 2 warp grid, 32x32 tiles
    const int g  = lane >> 2, tg = lane & 3;
    const bool small = (sel == 0) && (blockIdx.y >= 12);
    const __nv_bfloat16* A  = small ? g_q : (sel == 0) ? g_f : g_sampled;
    const __nv_bfloat16* Bw = small ? g_woaT : (sel == 0) ? g_wvT : g_woT;
    const float* bias = small ? g_boa : bias_in;
    const long rowBlock = (long)blockIdx.x * 128;
    const int  colBlock = small ? (blockIdx.y - 12) * 64 : blockIdx.y * 64;
    const int  nValid = small ? (NPAD - colBlock < 64 ? NPAD - colBlock : 64) : 64;

    // ---- load addressing: A 4 chunks (128 rows), B 2 chunks (64 rows) ----
    const int cr = tid >> 3, cc = tid & 7;         // base row (stride 32), chunk col
    const __nv_bfloat16* aG = A + (rowBlock + cr) * CDIM + cc * 8;
    const __nv_bfloat16* bG = Bw + ((long)colBlock + cr) * CDIM + cc * 8;
    const uint32_t d0 = (uint32_t)(cr * 128 + ((cc ^ (cr & 7)) * 16));
    int bSz[2]; long bOff[2];
    #pragma unroll
    for (int j = 0; j < 2; j++) {
        int ok = (cr + j * 32 < nValid);
        bSz[j]  = ok ? 16 : 0;
        bOff[j] = ok ? (long)j * (32 * CDIM) : 0;
    }

    auto load_stage = [&](int kt, int st) {
        uint32_t abase = sa + st * STAGE_BYTES + d0;
        uint32_t bbase = abase + A_SBYTES;
        const __nv_bfloat16* aP = aG + kt * 64;
        const __nv_bfloat16* bP = bG + kt * 64;
        #pragma unroll
        for (int j = 0; j < 4; j++)
            cpasync16(abase + j * 4096, aP + (long)j * (32 * CDIM));
        #pragma unroll
        for (int j = 0; j < 2; j++)
            cpasync16z(bbase + j * 4096, bP + bOff[j], bSz[j]);
        CP_COMMIT();
    };

    float acc[2][4][4];
    #pragma unroll
    for (int i = 0; i < 2; i++)
        #pragma unroll
        for (int j = 0; j < 4; j++)
            #pragma unroll
            for (int k = 0; k < 4; k++) acc[i][j][k] = 0.f;

    // ldmatrix per-lane precomputed addresses
    const int l15 = lane & 15, ls = lane >> 4, l7 = lane & 7;
    const uint32_t aRowB = (uint32_t)((wm * 32 + l15) * 128);
    const uint32_t bRowB = (uint32_t)((wn * 32 + l15) * 128) + A_SBYTES;
    uint32_t colT[4];
    #pragma unroll
    for (int kk = 0; kk < 4; kk++)
        colT[kk] = (uint32_t)(((kk * 2 + ls) ^ l7) * 16);

    auto compute = [&](int st) {
        uint32_t base = sa + st * STAGE_BYTES;
        uint32_t aB = base + aRowB, bB = base + bRowB;
        #pragma unroll
        for (int kk = 0; kk < 4; kk++) {
            uint32_t ct = colT[kk];
            uint32_t af[2][4], bf[2][4];
            #pragma unroll
            for (int mi = 0; mi < 2; mi++)
                ldsm4(af[mi], aB + (uint32_t)(mi * 2048) + ct);
            #pragma unroll
            for (int p = 0; p < 2; p++)
                ldsm4(bf[p], bB + (uint32_t)(p * 2048) + ct);
            #pragma unroll
            for (int mi = 0; mi < 2; mi++)
                #pragma unroll
                for (int ni = 0; ni < 4; ni++)
                    mma16816(acc[mi][ni], af[mi], bf[ni >> 1][ni & 1], bf[ni >> 1][(ni & 1) + 2]);
        }
    };

    load_stage(0, 0);
    load_stage(1, 1);
    int cur = 0;
    #pragma unroll 1
    for (int kt = 0; kt < KITERS; kt++) {
        CP_WAIT(1);
        __syncthreads();
        if (kt + 2 < KITERS) {
            int ld = cur + 2; if (ld >= 3) ld -= 3;
            load_stage(kt + 2, ld);
        } else {
            CP_COMMIT();     // keep group counting consistent
        }
        compute(cur);
        cur = (cur == 2) ? 0 : cur + 1;
    }

    // ---------------- epilogue (registers -> gmem) ----------------
    #pragma unroll
    for (int mi = 0; mi < 2; mi++) {
        #pragma unroll
        for (int ni = 0; ni < 4; ni++) {
            int r0 = (int)rowBlock + wm * 32 + mi * 16 + g;
            int c0 = colBlock + wn * 32 + ni * 8 + tg * 2;
            #pragma unroll
            for (int h = 0; h < 2; h++) {       // h=0: row r0, h=1: row r0+8
                int r = r0 + h * 8;
                float v0 = acc[mi][ni][h * 2], v1 = acc[mi][ni][h * 2 + 1];
                if (small) {
                    if (c0 < NOA)     g_raw[(long)r * NOA + c0]     = v0 + bias[c0];
                    if (c0 + 1 < NOA) g_raw[(long)r * NOA + c0 + 1] = v1 + bias[c0 + 1];
                } else if (sel == 0) {
                    float b0 = bias[c0], b1 = bias[c0 + 1];
                    __nv_bfloat162 t2 = __floats2bfloat162_rn(v0 + b0, v1 + b1);
                    *(__nv_bfloat162*)(g_value + (long)r * CDIM + c0) = t2;
                } else {
                    long idx = (long)r * CDIM + c0;
                    float2 xr = *(const float2*)(xres + idx);
                    float2 o;
                    o.x = xr.x + gamma[c0]     * (v0 + bias[c0]);
                    o.y = xr.y + gamma[c0 + 1] * (v1 + bias[c0 + 1]);
                    *(float2*)(outF + idx) = o;
                }
            }
        }
    }
}

// ---------------- softmax(4) + bilinear sampling (bf16 HFMA2) -----------------
__global__ __launch_bounds__(192) void sample_kernel(const float* __restrict__ refp) {
    __shared__ uint32_t s_w2[2][96];
    __shared__ uint32_t s_off[2][96];
    int t = threadIdx.x;
    int r = (t >= 96) ? 1 : 0;
    int j = t - r * 96;
    int row = blockIdx.x * 2 + r;
    int b = row >> 12;

    {
        int h = j >> 4, i = j & 15;        // head, corner (p*4+c)
        int p = i >> 2, c = i & 3;
        const float* raw = g_raw + (long)row * NOA;
        float lg0 = raw[48 + h * 4 + 0];
        float lg1 = raw[48 + h * 4 + 1];
        float lg2 = raw[48 + h * 4 + 2];
        float lg3 = raw[48 + h * 4 + 3];
        float mx = fmaxf(fmaxf(lg0, lg1), fmaxf(lg2, lg3));
        float e0 = __expf(lg0 - mx), e1 = __expf(lg1 - mx);
        float e2 = __expf(lg2 - mx), e3 = __expf(lg3 - mx);
        float inv = 1.f / (e0 + e1 + e2 + e3);
        float ap = ((p == 0) ? e0 : (p == 1) ? e1 : (p == 2) ? e2 : e3) * inv;

        float px = refp[row * 2]     * 64.f - 0.5f + raw[h * 8 + p * 2];
        float py = refp[row * 2 + 1] * 64.f - 0.5f + raw[h * 8 + p * 2 + 1];
        float x0f = floorf(px), y0f = floorf(py);
        float fx = px - x0f, fy = py - y0f;
        int x0 = (int)x0f, y0 = (int)y0f;
        float wx = (c & 1) ? fx : (1.f - fx);
        float wy = (c >> 1) ? fy : (1.f - fy);
        int yy = y0 + (c >> 1), xx = x0 + (c & 1);
        int yc = min(max(yy, 0), GH - 1), xc = min(max(xx, 0), GW - 1);
        float valid = (yy == yc && xx == xc) ? 1.f : 0.f;
        __nv_bfloat162 w2 = __float2bfloat162_rn(ap * wy * wx * valid);
        s_w2[r][j]  = *(uint32_t*)&w2;
        s_off[r][j] = (uint32_t)((yc * GW + xc) * CDIM) * 2u;   // byte offset
    }
    __syncthreads();

    int h = j >> 4, lane = j & 15;         // 8 dims per thread
    const char* vb = (const char*)(g_value + (long)b * 4096 * CDIM + h * HD + lane * 8);
    __nv_bfloat162 z; { float2 f0 = make_float2(0.f, 0.f); z = __floats2bfloat162_rn(f0.x, f0.y); }
    __nv_bfloat162 a0 = z, a1 = z, a2 = z, a3 = z;
    int base = h * 16;
    #pragma unroll
    for (int i = 0; i < 16; i++) {
        uint32_t w2u = s_w2[r][base + i];
        uint32_t off = s_off[r][base + i];
        uint4 v = *(const uint4*)(vb + off);
        __nv_bfloat162 w2 = *(__nv_bfloat162*)&w2u;
        a0 = __hfma2(w2, *(__nv_bfloat162*)&v.x, a0);
        a1 = __hfma2(w2, *(__nv_bfloat162*)&v.y, a1);
        a2 = __hfma2(w2, *(__nv_bfloat162*)&v.z, a2);
        a3 = __hfma2(w2, *(__nv_bfloat162*)&v.w, a3);
    }
    uint4 pk;
    pk.x = *(uint32_t*)&a0; pk.y = *(uint32_t*)&a1;
    pk.z = *(uint32_t*)&a2; pk.w = *(uint32_t*)&a3;
    *(uint4*)(g_sampled + (long)row * CDIM + h * HD + lane * 8) = pk;
}

// ---------------- launch ------------------------------------------------------
extern "C" void kernel_launch(void* const* d_in, const int* in_sizes, int n_in,
                              void* d_out, int out_size) {
    const float* x       = (const float*)d_in[0];
    const float* refp    = (const float*)d_in[1];
    const float* feat    = (const float*)d_in[2];
    const float* qn_w    = (const float*)d_in[5];
    const float* qn_b    = (const float*)d_in[6];
    const float* fn_w    = (const float*)d_in[7];
    const float* fn_b    = (const float*)d_in[8];
    const float* gamma   = (const float*)d_in[9];
    const float* w_value = (const float*)d_in[10];
    const float* b_value = (const float*)d_in[11];
    const float* w_off   = (const float*)d_in[12];
    const float* b_off   = (const float*)d_in[13];
    const float* w_attn  = (const float*)d_in[14];
    const float* b_attn  = (const float*)d_in[15];
    const float* w_out   = (const float*)d_in[16];
    const float* b_out   = (const float*)d_in[17];
    float* out = (float*)d_out;

    cudaFuncSetAttribute(gemm_tc, cudaFuncAttributeMaxDynamicSharedMemorySize, SMEM_DYN);

    ln_prep_kernel<<<LNROWS + PREPBLKS, 256>>>(x, feat, qn_w, qn_b, fn_w, fn_b,
                                               w_value, w_out, w_off, w_attn, b_off, b_attn);
    gemm_tc<<<dim3(64, 14), 256, SMEM_DYN>>>(0, b_value, nullptr, nullptr, nullptr);
    sample_kernel<<<MROWS / 2, 192>>>(refp);
    gemm_tc<<<dim3(64, 12), 256, SMEM_DYN>>>(2, b_out, x, gamma, out);
}

// round 16
// speedup vs baseline: 1.0766x; 1.0766x over previous
#include <cuda_runtime.h>
#include <cuda_bf16.h>
#include <cuda_fp8.h>
#include <cstdint>

#define BB    2
#define LQ    4096
#define CDIM  768
#define GH    64
#define GW    64
#define NHEAD 6
#define NPNT  4
#define HD    128
#define MROWS 8192      // B*Lq == B*H*W
#define NOA   72        // off(48) + attn(24) columns
#define NPAD  96        // padded N rows for small GEMM weights
#define KITERS 6        // 768 / 128 (fp8: 128 elems per 128B row)
#define STAGES 3
#define STAGE_BYTES 32768   // A 128x128B + B 128x128B (swizzled)
#define SMEM_DYN (STAGES * STAGE_BYTES)
#define LNROWS (2 * MROWS)
#define PREPBLKS (1153 + 288)

// ---------------- scratch (device globals; no allocation allowed) -------------
__device__ __align__(16) uint8_t       g_q8[MROWS * CDIM];
__device__ __align__(16) uint8_t       g_f8[MROWS * CDIM];
__device__ __align__(16) __nv_bfloat16 g_value[MROWS * CDIM];
__device__ __align__(16) uint8_t       g_sampled8[MROWS * CDIM];
__device__ __align__(16) float         g_raw[MROWS * NOA];
__device__ __align__(16) uint8_t       g_wvT8[CDIM * CDIM];   // [N][K] e4m3
__device__ __align__(16) uint8_t       g_woT8[CDIM * CDIM];   // [N][K] e4m3
__device__ __align__(16) uint8_t       g_woaT8[NPAD * CDIM];  // [N=96][K] e4m3
__device__ __align__(16) float         g_boa[NPAD];

// ---------------- PTX helpers -------------------------------------------------
__device__ __forceinline__ uint32_t smem_u32(const void* p) {
    uint32_t a;
    asm("{ .reg .u64 t; cvta.to.shared.u64 t, %1; cvt.u32.u64 %0, t; }" : "=r"(a) : "l"(p));
    return a;
}
__device__ __forceinline__ void cpasync16(uint32_t s, const void* g) {
    asm volatile("cp.async.cg.shared.global [%0], [%1], 16;" :: "r"(s), "l"(g));
}
__device__ __forceinline__ void cpasync16z(uint32_t s, const void* g, int srcsz) {
    asm volatile("cp.async.cg.shared.global [%0], [%1], 16, %2;" :: "r"(s), "l"(g), "r"(srcsz));
}
#define CP_COMMIT() asm volatile("cp.async.commit_group;" ::: "memory")
#define CP_WAIT(n)  asm volatile("cp.async.wait_group %0;" :: "n"(n) : "memory")

__device__ __forceinline__ void ldsm4(uint32_t r[4], uint32_t addr) {
    asm volatile("ldmatrix.sync.aligned.m8n8.x4.shared.b16 {%0,%1,%2,%3}, [%4];"
                 : "=r"(r[0]), "=r"(r[1]), "=r"(r[2]), "=r"(r[3]) : "r"(addr));
}
// fp8 e4m3 MMA: same reg shape as bf16 m16n8k16 (A:4, B:2, C:4), K=32 bytes
__device__ __forceinline__ void mma_fp8(float c[4], const uint32_t a[4], uint32_t b0, uint32_t b1) {
    asm volatile(
        "mma.sync.aligned.m16n8k32.row.col.f32.e4m3.e4m3.f32 "
        "{%0,%1,%2,%3},{%4,%5,%6,%7},{%8,%9},{%0,%1,%2,%3};\n"
        : "+f"(c[0]), "+f"(c[1]), "+f"(c[2]), "+f"(c[3])
        : "r"(a[0]), "r"(a[1]), "r"(a[2]), "r"(a[3]), "r"(b0), "r"(b1));
}
__device__ __forceinline__ uint8_t f2e4m3(float v) {
    return (uint8_t)__nv_cvt_float_to_fp8(v, __NV_SATFINITE, __NV_E4M3);
}
__device__ __forceinline__ uint16_t f22e4m3(float lo, float hi) {
    return (uint16_t)__nv_cvt_float2_to_fp8x2(make_float2(lo, hi), __NV_SATFINITE, __NV_E4M3);
}

// ---------------- fused LN + weight prep (single launch) ----------------------
// blocks [0, 16384): dual LayerNorm (fp8 out), one row each (192 active threads)
// blocks [16384, +1152): 32x32 transpose tiles (wv / wo) -> fp8
// block  +1152: pack small-GEMM bias; blocks after: pack woaT -> fp8
__global__ __launch_bounds__(256) void ln_prep_kernel(
    const float* __restrict__ x, const float* __restrict__ feat,
    const float* __restrict__ qw, const float* __restrict__ qb,
    const float* __restrict__ fw, const float* __restrict__ fb,
    const float* __restrict__ wv, const float* __restrict__ wo,
    const float* __restrict__ woff, const float* __restrict__ watt,
    const float* __restrict__ boff, const float* __restrict__ batt) {
    int blkid = blockIdx.x;
    int tid = threadIdx.x;
    if (blkid < LNROWS) {
        if (tid >= 192) return;
        int row = blkid;
        int t = tid;
        const float *src, *w, *bb;
        uint8_t* dst;
        if (row < MROWS) {
            src = x + (long)row * CDIM; w = qw; bb = qb; dst = g_q8 + (long)row * CDIM;
        } else {
            int r = row - MROWS;
            src = feat + (long)r * CDIM; w = fw; bb = fb; dst = g_f8 + (long)r * CDIM;
        }
        float4 v = *(const float4*)(src + t * 4);
        float s  = v.x + v.y + v.z + v.w;
        float ss = v.x * v.x + v.y * v.y + v.z * v.z + v.w * v.w;
        #pragma unroll
        for (int o = 16; o > 0; o >>= 1) {
            s  += __shfl_xor_sync(0xffffffffu, s,  o);
            ss += __shfl_xor_sync(0xffffffffu, ss, o);
        }
        __shared__ float sm[12];
        if ((t & 31) == 0) { sm[t >> 5] = s; sm[(t >> 5) + 6] = ss; }
        __syncthreads();
        float S = 0.f, SS = 0.f;
        #pragma unroll
        for (int i = 0; i < 6; i++) { S += sm[i]; SS += sm[i + 6]; }
        float mean = S * (1.f / 768.f);
        float var  = SS * (1.f / 768.f) - mean * mean;
        float inv  = rsqrtf(var + 1e-6f);
        float4 wv4 = *(const float4*)(w + t * 4);
        float4 bv4 = *(const float4*)(bb + t * 4);
        float n0 = (v.x - mean) * inv * wv4.x + bv4.x;
        float n1 = (v.y - mean) * inv * wv4.y + bv4.y;
        float n2 = (v.z - mean) * inv * wv4.z + bv4.z;
        float n3 = (v.w - mean) * inv * wv4.w + bv4.w;
        uint32_t pk = (uint32_t)f22e4m3(n0, n1) | ((uint32_t)f22e4m3(n2, n3) << 16);
        *(uint32_t*)(dst + t * 4) = pk;
        return;
    }
    int blk = blkid - LNROWS;
    if (blk < 1152) {
        __shared__ float t[32][33];
        int z = blk / 576, rem = blk % 576;
        const float* src = z ? wo : wv;
        uint8_t* dst = z ? g_woT8 : g_wvT8;
        int bx = (rem % 24) * 32, by = (rem / 24) * 32;
        int tx = tid & 31, ty = tid >> 5;          // 32 x 8
        #pragma unroll
        for (int i = 0; i < 32; i += 8)
            t[ty + i][tx] = src[(long)(by + ty + i) * CDIM + bx + tx];
        __syncthreads();
        #pragma unroll
        for (int i = 0; i < 32; i += 8)
            dst[(long)(bx + ty + i) * CDIM + by + tx] = f2e4m3(t[tx][ty + i]);
    } else if (blk == 1152) {
        if (tid < NPAD)
            g_boa[tid] = (tid < 48) ? boff[tid] : (tid < NOA) ? batt[tid - 48] : 0.f;
    } else {
        int i = (blk - 1153) * 256 + tid;
        if (i < NPAD * CDIM) {
            int n = i / CDIM, k = i % CDIM;
            float v = (n < 48) ? woff[k * 48 + n] : (n < NOA) ? watt[k * 24 + (n - 48)] : 0.f;
            g_woaT8[i] = f2e4m3(v);
        }
    }
}

// ---------------- fp8 mma.sync GEMM: CTA 128x128, 8 warps 64x32, 2 CTA/SM -----
// 3-stage cp.async, k-chunk 128 (128B rows), swizzled. KITERS=6.
// sel 0: y<6: g_f8 @ wvT8 -> g_value (bf16,+bias); y==6: g_q8 @ woaT8 -> g_raw
// sel 2: g_sampled8 @ woT8, out = x + gamma*(acc+bias)
__global__ __launch_bounds__(256, 2) void gemm_tc(
    int sel,
    const float* __restrict__ bias_in,
    const float* __restrict__ xres, const float* __restrict__ gamma,
    float* __restrict__ outF)
{
    extern __shared__ __align__(16) char smem[];
    const uint32_t sa = smem_u32(smem);

    const int tid = threadIdx.x;
    const int warp = tid >> 5, lane = tid & 31;
    const int wm = warp >> 2, wn = warp & 3;       // 2 x 4 warp grid
    const int g  = lane >> 2, tg = lane & 3;
    const bool small = (sel == 0) && (blockIdx.y == 6);
    const uint8_t* A  = small ? g_q8 : (sel == 0) ? g_f8 : g_sampled8;
    const uint8_t* Bw = small ? g_woaT8 : (sel == 0) ? g_wvT8 : g_woT8;
    const float* bias = small ? g_boa : bias_in;
    const int nRows = small ? NPAD : 128;          // valid B tile rows
    const long rowBlock = (long)blockIdx.x * 128;
    const int  colBlock = small ? 0 : blockIdx.y * 128;

    // ---- hoisted per-thread load addressing (bytes; 128B per k-chunk row) ----
    const int cr = tid >> 3, cc = tid & 7;         // base row (stride 32), 16B chunk col
    const uint8_t* aG = A + (rowBlock + cr) * CDIM + cc * 16;
    const uint8_t* bG = Bw + ((long)colBlock) * CDIM + cc * 16;
    uint32_t dOff[4]; long bRow[4]; int bSz[4];
    #pragma unroll
    for (int j = 0; j < 4; j++) {
        int r = cr + j * 32;
        dOff[j] = (uint32_t)(r * 128 + ((cc ^ (r & 7)) * 16));
        bSz[j]  = (r < nRows) ? 16 : 0;
        bRow[j] = (long)((r < nRows) ? r : 0) * CDIM;
    }

    auto load_stage = [&](int kt, int st) {
        uint32_t abase = sa + st * STAGE_BYTES;
        uint32_t bbase = abase + 16384;
        const uint8_t* aP = aG + kt * 128;
        const uint8_t* bP = bG + kt * 128;
        #pragma unroll
        for (int j = 0; j < 4; j++) {
            cpasync16(abase + dOff[j], aP + (long)j * (32 * CDIM));
            cpasync16z(bbase + dOff[j], bP + bRow[j], bSz[j]);
        }
        CP_COMMIT();
    };

    float acc[4][4][4];
    #pragma unroll
    for (int i = 0; i < 4; i++)
        #pragma unroll
        for (int j = 0; j < 4; j++)
            #pragma unroll
            for (int k = 0; k < 4; k++) acc[i][j][k] = 0.f;

    // ldmatrix per-lane precomputed addresses (identical swizzle to bf16 path)
    const int l15 = lane & 15, ls = lane >> 4, l7 = lane & 7;
    const uint32_t aRowB = (uint32_t)((wm * 64 + l15) * 128);
    const uint32_t bRowB = (uint32_t)((wn * 32 + l15) * 128) + 16384;
    uint32_t colT[4];
    #pragma unroll
    for (int kk = 0; kk < 4; kk++)
        colT[kk] = (uint32_t)(((kk * 2 + ls) ^ l7) * 16);

    auto compute = [&](int st) {
        uint32_t base = sa + st * STAGE_BYTES;
        uint32_t aB = base + aRowB, bB = base + bRowB;
        #pragma unroll
        for (int kk = 0; kk < 4; kk++) {           // 4 x k32 = 128 fp8 per chunk
            uint32_t ct = colT[kk];
            uint32_t af[4][4], bf[2][4];
            #pragma unroll
            for (int mi = 0; mi < 4; mi++)
                ldsm4(af[mi], aB + (uint32_t)(mi * 2048) + ct);
            #pragma unroll
            for (int p = 0; p < 2; p++)
                ldsm4(bf[p], bB + (uint32_t)(p * 2048) + ct);
            #pragma unroll
            for (int mi = 0; mi < 4; mi++)
                #pragma unroll
                for (int ni = 0; ni < 4; ni++)
                    mma_fp8(acc[mi][ni], af[mi], bf[ni >> 1][ni & 1], bf[ni >> 1][(ni & 1) + 2]);
        }
    };

    load_stage(0, 0);
    load_stage(1, 1);
    int cur = 0;
    #pragma unroll 1
    for (int kt = 0; kt < KITERS; kt++) {
        CP_WAIT(1);
        __syncthreads();
        if (kt + 2 < KITERS) {
            int ld = cur + 2; if (ld >= 3) ld -= 3;
            load_stage(kt + 2, ld);
        } else {
            CP_COMMIT();     // keep group counting consistent
        }
        compute(cur);
        cur = (cur == 2) ? 0 : cur + 1;
    }

    // ---------------- epilogue (registers -> gmem) ----------------
    #pragma unroll
    for (int mi = 0; mi < 4; mi++) {
        #pragma unroll
        for (int ni = 0; ni < 4; ni++) {
            int r0 = (int)rowBlock + wm * 64 + mi * 16 + g;
            int c0 = colBlock + wn * 32 + ni * 8 + tg * 2;
            #pragma unroll
            for (int h = 0; h < 2; h++) {       // h=0: row r0, h=1: row r0+8
                int r = r0 + h * 8;
                float v0 = acc[mi][ni][h * 2], v1 = acc[mi][ni][h * 2 + 1];
                if (small) {
                    if (c0 < NOA)     g_raw[(long)r * NOA + c0]     = v0 + bias[c0];
                    if (c0 + 1 < NOA) g_raw[(long)r * NOA + c0 + 1] = v1 + bias[c0 + 1];
                } else if (sel == 0) {
                    float b0 = bias[c0], b1 = bias[c0 + 1];
                    __nv_bfloat162 t2 = __floats2bfloat162_rn(v0 + b0, v1 + b1);
                    *(__nv_bfloat162*)(g_value + (long)r * CDIM + c0) = t2;
                } else {
                    long idx = (long)r * CDIM + c0;
                    float2 xr = *(const float2*)(xres + idx);
                    float2 o;
                    o.x = xr.x + gamma[c0]     * (v0 + bias[c0]);
                    o.y = xr.y + gamma[c0 + 1] * (v1 + bias[c0 + 1]);
                    *(float2*)(outF + idx) = o;
                }
            }
        }
    }
}

// ---------------- softmax(4) + bilinear sampling (bf16 HFMA2, fp8 out) --------
// 2 rows per block, 192 threads. Thread t -> (row r = t>=96, slot j = t%96).
__global__ __launch_bounds__(192) void sample_kernel(const float* __restrict__ refp) {
    __shared__ uint32_t s_w2[2][96];
    __shared__ uint32_t s_off[2][96];
    int t = threadIdx.x;
    int r = (t >= 96) ? 1 : 0;
    int j = t - r * 96;
    int row = blockIdx.x * 2 + r;
    int b = row >> 12;

    {
        int h = j >> 4, i = j & 15;        // head, corner (p*4+c)
        int p = i >> 2, c = i & 3;
        const float* raw = g_raw + (long)row * NOA;
        float lg0 = raw[48 + h * 4 + 0];
        float lg1 = raw[48 + h * 4 + 1];
        float lg2 = raw[48 + h * 4 + 2];
        float lg3 = raw[48 + h * 4 + 3];
        float mx = fmaxf(fmaxf(lg0, lg1), fmaxf(lg2, lg3));
        float e0 = __expf(lg0 - mx), e1 = __expf(lg1 - mx);
        float e2 = __expf(lg2 - mx), e3 = __expf(lg3 - mx);
        float inv = 1.f / (e0 + e1 + e2 + e3);
        float ap = ((p == 0) ? e0 : (p == 1) ? e1 : (p == 2) ? e2 : e3) * inv;

        float px = refp[row * 2]     * 64.f - 0.5f + raw[h * 8 + p * 2];
        float py = refp[row * 2 + 1] * 64.f - 0.5f + raw[h * 8 + p * 2 + 1];
        float x0f = floorf(px), y0f = floorf(py);
        float fx = px - x0f, fy = py - y0f;
        int x0 = (int)x0f, y0 = (int)y0f;
        float wx = (c & 1) ? fx : (1.f - fx);
        float wy = (c >> 1) ? fy : (1.f - fy);
        int yy = y0 + (c >> 1), xx = x0 + (c & 1);
        int yc = min(max(yy, 0), GH - 1), xc = min(max(xx, 0), GW - 1);
        float valid = (yy == yc && xx == xc) ? 1.f : 0.f;
        __nv_bfloat162 w2 = __float2bfloat162_rn(ap * wy * wx * valid);
        s_w2[r][j]  = *(uint32_t*)&w2;
        s_off[r][j] = (uint32_t)((yc * GW + xc) * CDIM) * 2u;   // byte offset
    }
    __syncthreads();

    int h = j >> 4, lane = j & 15;         // 8 dims per thread
    const char* vb = (const char*)(g_value + (long)b * 4096 * CDIM + h * HD + lane * 8);
    __nv_bfloat162 z; { float2 f0 = make_float2(0.f, 0.f); z = __floats2bfloat162_rn(f0.x, f0.y); }
    __nv_bfloat162 a0 = z, a1 = z, a2 = z, a3 = z;
    int base = h * 16;
    #pragma unroll
    for (int i = 0; i < 16; i++) {
        uint32_t w2u = s_w2[r][base + i];
        uint32_t off = s_off[r][base + i];
        uint4 v = *(const uint4*)(vb + off);
        __nv_bfloat162 w2 = *(__nv_bfloat162*)&w2u;
        a0 = __hfma2(w2, *(__nv_bfloat162*)&v.x, a0);
        a1 = __hfma2(w2, *(__nv_bfloat162*)&v.y, a1);
        a2 = __hfma2(w2, *(__nv_bfloat162*)&v.z, a2);
        a3 = __hfma2(w2, *(__nv_bfloat162*)&v.w, a3);
    }
    float2 f0 = __bfloat1622float2(a0);
    float2 f1 = __bfloat1622float2(a1);
    float2 f2 = __bfloat1622float2(a2);
    float2 f3 = __bfloat1622float2(a3);
    uint2 pk;
    pk.x = (uint32_t)f22e4m3(f0.x, f0.y) | ((uint32_t)f22e4m3(f1.x, f1.y) << 16);
    pk.y = (uint32_t)f22e4m3(f2.x, f2.y) | ((uint32_t)f22e4m3(f3.x, f3.y) << 16);
    *(uint2*)(g_sampled8 + (long)row * CDIM + h * HD + lane * 8) = pk;
}

// ---------------- launch ------------------------------------------------------
extern "C" void kernel_launch(void* const* d_in, const int* in_sizes, int n_in,
                              void* d_out, int out_size) {
    const float* x       = (const float*)d_in[0];
    const float* refp    = (const float*)d_in[1];
    const float* feat    = (const float*)d_in[2];
    const float* qn_w    = (const float*)d_in[5];
    const float* qn_b    = (const float*)d_in[6];
    const float* fn_w    = (const float*)d_in[7];
    const float* fn_b    = (const float*)d_in[8];
    const float* gamma   = (const float*)d_in[9];
    const float* w_value = (const float*)d_in[10];
    const float* b_value = (const float*)d_in[11];
    const float* w_off   = (const float*)d_in[12];
    const float* b_off   = (const float*)d_in[13];
    const float* w_attn  = (const float*)d_in[14];
    const float* b_attn  = (const float*)d_in[15];
    const float* w_out   = (const float*)d_in[16];
    const float* b_out   = (const float*)d_in[17];
    float* out = (float*)d_out;

    cudaFuncSetAttribute(gemm_tc, cudaFuncAttributeMaxDynamicSharedMemorySize, SMEM_DYN);

    ln_prep_kernel<<<LNROWS + PREPBLKS, 256>>>(x, feat, qn_w, qn_b, fn_w, fn_b,
                                               w_value, w_out, w_off, w_attn, b_off, b_attn);
    gemm_tc<<<dim3(64, 7), 256, SMEM_DYN>>>(0, b_value, nullptr, nullptr, nullptr);
    sample_kernel<<<MROWS / 2, 192>>>(refp);
    gemm_tc<<<dim3(64, 6), 256, SMEM_DYN>>>(2, b_out, x, gamma, out);
}